// round 1
// baseline (speedup 1.0000x reference)
#include <cuda_runtime.h>
#include <cuda_bf16.h>

// Problem constants
#define BATCH   4
#define TSEQ    4096
#define DEMB    512
#define DH      64
#define NTOK    (BATCH * TSEQ)   // 16384

// Scratch for Q, K, V projections (fp32), [B*T, 64] row-major each.
__device__ float g_Q[NTOK * DH];
__device__ float g_K[NTOK * DH];
__device__ float g_V[NTOK * DH];

// ---------------------------------------------------------------------------
// Kernel 1: fused QKV projection.  C = X @ W^T + b for W in {Wq,Wk,Wv}.
// X: [16384, 512] row-major.  W: [64, 512] row-major.  C: [16384, 64].
// Block tile: 64 rows x 64 cols (all of one matrix), BK = 32.
// 256 threads, 16x16 thread grid, 4x4 register tile per thread.
// Smem tiles stored k-major (transposed) with pitch 68 so GEMM reads are
// conflict-free float4 broadcasts / strided LDS.128.
// ---------------------------------------------------------------------------
__global__ __launch_bounds__(256) void qkv_kernel(
    const float* __restrict__ X,
    const float* __restrict__ Wq, const float* __restrict__ bq,
    const float* __restrict__ Wk, const float* __restrict__ bk,
    const float* __restrict__ Wv, const float* __restrict__ bv)
{
    __shared__ float Xt[32 * 68];   // Xt[kk][row]
    __shared__ float Wt[32 * 68];   // Wt[kk][col]

    const int m0    = blockIdx.x * 64;
    const int which = blockIdx.y;

    const float* W    = (which == 0) ? Wq : (which == 1) ? Wk : Wv;
    const float* bias = (which == 0) ? bq : (which == 1) ? bk : bv;
    float*       Cout = (which == 0) ? g_Q : (which == 1) ? g_K : g_V;

    const int tid = threadIdx.x;
    const int tx  = tid & 15;
    const int ty  = tid >> 4;

    float acc[4][4];
    #pragma unroll
    for (int i = 0; i < 4; i++)
        #pragma unroll
        for (int j = 0; j < 4; j++) acc[i][j] = 0.f;

    for (int kb = 0; kb < DEMB; kb += 32) {
        __syncthreads();
        // Load X tile [64 rows][32 k] transposed into Xt[kk][r]
        #pragma unroll
        for (int it = 0; it < 8; it++) {
            int e  = tid + it * 256;         // 0..2047
            int r  = e >> 5;                 // 0..63
            int kk = e & 31;                 // 0..31
            Xt[kk * 68 + r] = X[(size_t)(m0 + r) * DEMB + kb + kk];
        }
        // Load W tile [64 cols][32 k] transposed into Wt[kk][c]
        #pragma unroll
        for (int it = 0; it < 8; it++) {
            int e  = tid + it * 256;
            int c  = e >> 5;
            int kk = e & 31;
            Wt[kk * 68 + c] = W[(size_t)c * DEMB + kb + kk];
        }
        __syncthreads();

        #pragma unroll 8
        for (int kk = 0; kk < 32; kk++) {
            float4 a  = *(const float4*)(Xt + kk * 68 + 4 * ty);
            float4 bb = *(const float4*)(Wt + kk * 68 + 4 * tx);
            const float* ap = (const float*)&a;
            const float* bp = (const float*)&bb;
            #pragma unroll
            for (int i = 0; i < 4; i++)
                #pragma unroll
                for (int j = 0; j < 4; j++)
                    acc[i][j] += ap[i] * bp[j];
        }
    }

    // Bias + store (coalesced float4)
    float4 bb4 = *(const float4*)(bias + 4 * tx);
    const float* bp = (const float*)&bb4;
    #pragma unroll
    for (int i = 0; i < 4; i++) {
        int row = m0 + 4 * ty + i;
        float4 v = make_float4(acc[i][0] + bp[0], acc[i][1] + bp[1],
                               acc[i][2] + bp[2], acc[i][3] + bp[3]);
        *(float4*)(Cout + (size_t)row * DH + 4 * tx) = v;
    }
}

// ---------------------------------------------------------------------------
// Kernel 2: causal flash attention, fp32.
//   scores = Q K^T (raw, no pre-scale), causal mask, online softmax,
//   out = softmax(scores) @ V * sqrt(64)  (post-softmax scale = 8).
// One block = (batch b, query tile of 64 rows). BK = 64. 256 threads.
// Smem: Qt/Kt d-major pitch 68 (conflict-free float4 GEMM loads),
//       Vs row-major pitch 64, Ps row-major pitch 64.
// ---------------------------------------------------------------------------
#define QT_PITCH 68
#define SMEM_ATTN ((2 * 64 * QT_PITCH + 2 * 64 * 64) * 4)   // 67584 bytes

__global__ __launch_bounds__(256) void attn_kernel(float* __restrict__ Out)
{
    extern __shared__ float sm[];
    float* Qt = sm;                       // [64][68]  Qt[d][r]
    float* Kt = sm + 64 * QT_PITCH;       // [64][68]  Kt[d][j]
    float* Vs = sm + 2 * 64 * QT_PITCH;   // [64][64]  Vs[j][d]
    float* Ps = Vs + 64 * 64;             // [64][64]  Ps[r][j]

    const int bi = blockIdx.x;
    const int b  = bi & 3;
    const int qt = (TSEQ / 64 - 1) - (bi >> 2);   // heaviest tiles first

    const int tid = threadIdx.x;
    const int tx  = tid & 15;
    const int ty  = tid >> 4;

    const size_t base = (size_t)b * TSEQ * DH;
    const int q0 = qt * 64;

    // Load Q tile transposed: Qt[d][r] = Q[q0+r][d]
    #pragma unroll
    for (int it = 0; it < 16; it++) {
        int e = tid + it * 256;      // 0..4095
        int r = e >> 6;
        int d = e & 63;
        Qt[d * QT_PITCH + r] = g_Q[base + (size_t)(q0 + r) * DH + d];
    }

    float O[4][4];
    float m_run[4], l_run[4];
    #pragma unroll
    for (int i = 0; i < 4; i++) {
        m_run[i] = -1e30f;
        l_run[i] = 0.f;
        #pragma unroll
        for (int j = 0; j < 4; j++) O[i][j] = 0.f;
    }

    for (int kt = 0; kt <= qt; kt++) {
        const int k0 = kt * 64;
        __syncthreads();   // prev iter done reading Kt/Vs/Ps

        // Load K tile transposed: Kt[d][j] = K[k0+j][d]
        #pragma unroll
        for (int it = 0; it < 16; it++) {
            int e = tid + it * 256;
            int r = e >> 6;
            int d = e & 63;
            Kt[d * QT_PITCH + r] = g_K[base + (size_t)(k0 + r) * DH + d];
        }
        // Load V tile row-major (straight float4 copy of 16 KB)
        #pragma unroll
        for (int it = 0; it < 4; it++) {
            int e = tid + it * 256;  // float4 index, 0..1023
            *(float4*)(Vs + e * 4) =
                *(const float4*)(g_V + base + (size_t)k0 * DH + e * 4);
        }
        __syncthreads();

        // --- GEMM1: S[4][4] = Q_tile @ K_tile^T (this thread's 4x4) ---
        float S[4][4];
        #pragma unroll
        for (int i = 0; i < 4; i++)
            #pragma unroll
            for (int j = 0; j < 4; j++) S[i][j] = 0.f;

        #pragma unroll 8
        for (int d = 0; d < 64; d++) {
            float4 a  = *(const float4*)(Qt + d * QT_PITCH + 4 * ty);
            float4 bb = *(const float4*)(Kt + d * QT_PITCH + 4 * tx);
            const float* ap = (const float*)&a;
            const float* bp = (const float*)&bb;
            #pragma unroll
            for (int i = 0; i < 4; i++)
                #pragma unroll
                for (int j = 0; j < 4; j++)
                    S[i][j] += ap[i] * bp[j];
        }

        // --- causal mask (only the diagonal tile needs it) ---
        if (kt == qt) {
            #pragma unroll
            for (int i = 0; i < 4; i++) {
                int q = q0 + 4 * ty + i;
                #pragma unroll
                for (int j = 0; j < 4; j++) {
                    int k = k0 + 4 * tx + j;
                    if (k > q) S[i][j] = -1e30f;
                }
            }
        }

        // --- online softmax (row reductions over 16 lanes via shfl) ---
        #pragma unroll
        for (int i = 0; i < 4; i++) {
            float m = fmaxf(fmaxf(S[i][0], S[i][1]), fmaxf(S[i][2], S[i][3]));
            m = fmaxf(m, __shfl_xor_sync(0xffffffffu, m, 1));
            m = fmaxf(m, __shfl_xor_sync(0xffffffffu, m, 2));
            m = fmaxf(m, __shfl_xor_sync(0xffffffffu, m, 4));
            m = fmaxf(m, __shfl_xor_sync(0xffffffffu, m, 8));

            float m_new = fmaxf(m_run[i], m);
            float scale = __expf(m_run[i] - m_new);
            m_run[i] = m_new;

            float rs = 0.f;
            #pragma unroll
            for (int j = 0; j < 4; j++) {
                S[i][j] = __expf(S[i][j] - m_new);
                rs += S[i][j];
            }
            rs += __shfl_xor_sync(0xffffffffu, rs, 1);
            rs += __shfl_xor_sync(0xffffffffu, rs, 2);
            rs += __shfl_xor_sync(0xffffffffu, rs, 4);
            rs += __shfl_xor_sync(0xffffffffu, rs, 8);

            l_run[i] = l_run[i] * scale + rs;
            O[i][0] *= scale; O[i][1] *= scale;
            O[i][2] *= scale; O[i][3] *= scale;
        }

        // Write P tile to smem (STS.128, conflict-free)
        #pragma unroll
        for (int i = 0; i < 4; i++) {
            float4 p = make_float4(S[i][0], S[i][1], S[i][2], S[i][3]);
            *(float4*)(Ps + (4 * ty + i) * 64 + 4 * tx) = p;
        }
        __syncthreads();

        // --- GEMM2: O += P @ V ---
        #pragma unroll 4
        for (int j0 = 0; j0 < 64; j0 += 4) {
            float4 av[4], bv[4];
            #pragma unroll
            for (int i = 0; i < 4; i++)
                av[i] = *(const float4*)(Ps + (4 * ty + i) * 64 + j0);
            #pragma unroll
            for (int jj = 0; jj < 4; jj++)
                bv[jj] = *(const float4*)(Vs + (j0 + jj) * 64 + 4 * tx);
            #pragma unroll
            for (int i = 0; i < 4; i++) {
                const float* ap = (const float*)&av[i];
                #pragma unroll
                for (int jj = 0; jj < 4; jj++) {
                    float p = ap[jj];
                    O[i][0] += p * ((const float*)&bv[jj])[0];
                    O[i][1] += p * ((const float*)&bv[jj])[1];
                    O[i][2] += p * ((const float*)&bv[jj])[2];
                    O[i][3] += p * ((const float*)&bv[jj])[3];
                }
            }
        }
    }

    // Normalize, apply post-softmax sqrt(d_h)=8 scale, store.
    #pragma unroll
    for (int i = 0; i < 4; i++) {
        float sc = 8.0f / l_run[i];
        float4 o = make_float4(O[i][0] * sc, O[i][1] * sc,
                               O[i][2] * sc, O[i][3] * sc);
        *(float4*)(Out + base + (size_t)(q0 + 4 * ty + i) * DH + 4 * tx) = o;
    }
}

// ---------------------------------------------------------------------------
// Launch: inputs per metadata order: x, Wq_w, Wq_b, Wk_w, Wk_b, Wv_w, Wv_b
// ---------------------------------------------------------------------------
extern "C" void kernel_launch(void* const* d_in, const int* in_sizes, int n_in,
                              void* d_out, int out_size)
{
    const float* x  = (const float*)d_in[0];
    const float* Wq = (const float*)d_in[1];
    const float* bq = (const float*)d_in[2];
    const float* Wk = (const float*)d_in[3];
    const float* bk = (const float*)d_in[4];
    const float* Wv = (const float*)d_in[5];
    const float* bv = (const float*)d_in[6];
    float* out = (float*)d_out;

    // QKV projections: 256 row-tiles x 3 matrices
    qkv_kernel<<<dim3(256, 3), 256>>>(x, Wq, bq, Wk, bk, Wv, bv);

    // Flash attention: 64 query tiles x 4 batches
    cudaFuncSetAttribute(attn_kernel,
                         cudaFuncAttributeMaxDynamicSharedMemorySize,
                         SMEM_ATTN);
    attn_kernel<<<256, 256, SMEM_ATTN>>>(out);
}

// round 3
// speedup vs baseline: 1.5565x; 1.5565x over previous
#include <cuda_runtime.h>
#include <cuda_bf16.h>
#include <stdint.h>

// Problem constants
#define BATCH   4
#define TSEQ    4096
#define DEMB    512
#define DH      64
#define NTOK    (BATCH * TSEQ)   // 16384

// ---------------------------------------------------------------------------
// Global scratch: bf16 hi/lo split of Q, K (row-major [b*t][64]) and V
// transposed ([b][64 d][4096 t]) produced by the QKV kernel.
// ---------------------------------------------------------------------------
__device__ __nv_bfloat16 g_Qh[NTOK * DH];
__device__ __nv_bfloat16 g_Ql[NTOK * DH];
__device__ __nv_bfloat16 g_Kh[NTOK * DH];
__device__ __nv_bfloat16 g_Kl[NTOK * DH];
__device__ __nv_bfloat16 g_Vth[NTOK * DH];
__device__ __nv_bfloat16 g_Vtl[NTOK * DH];

// ---------------------------------------------------------------------------
// Helpers
// ---------------------------------------------------------------------------
__device__ __forceinline__ uint32_t smem_u32(const void* p) {
    uint32_t a;
    asm("{ .reg .u64 t; cvta.to.shared.u64 t, %1; cvt.u32.u64 %0, t; }"
        : "=r"(a) : "l"(p));
    return a;
}

#define SWZ(o) ((o) ^ (((o) >> 3) & 0x70))

#define LDSM_X4(r, addr) \
    asm volatile("ldmatrix.sync.aligned.m8n8.x4.shared.b16 {%0,%1,%2,%3}, [%4];" \
        : "=r"((r)[0]), "=r"((r)[1]), "=r"((r)[2]), "=r"((r)[3]) : "r"(addr))
#define LDSM_X2(r, addr) \
    asm volatile("ldmatrix.sync.aligned.m8n8.x2.shared.b16 {%0,%1}, [%2];" \
        : "=r"((r)[0]), "=r"((r)[1]) : "r"(addr))

// m16n8k16 bf16 -> f32 accumulate (HMMA)
__device__ __forceinline__ void mma_bf16(float* c, const uint32_t* a, const uint32_t* b) {
    asm volatile(
        "mma.sync.aligned.m16n8k16.row.col.f32.bf16.bf16.f32 "
        "{%0,%1,%2,%3}, {%4,%5,%6,%7}, {%8,%9}, {%0,%1,%2,%3};"
        : "+f"(c[0]), "+f"(c[1]), "+f"(c[2]), "+f"(c[3])
        : "r"(a[0]), "r"(a[1]), "r"(a[2]), "r"(a[3]), "r"(b[0]), "r"(b[1]));
}

#define L2E 1.44269504088896f

// Fast exp2 on the FMA/ALU pipes (no MUFU). t <= ~0 expected; clamps to -126.
// Max rel err ~4e-5 (deg-4 Taylor on |f ln2| <= 0.347).
__device__ __forceinline__ float exp2ap(float t) {
    t = fmaxf(t, -126.0f);
    float r = t + 12582912.0f;                       // round-to-nearest-int magic
    int   n = __float_as_int(r) - 0x4B400000;        // integer part
    float f = t - (r - 12582912.0f);                 // frac in [-0.5, 0.5]
    float p = fmaf(f, 0.00961813f, 0.05550411f);
    p = fmaf(f, p, 0.24022651f);
    p = fmaf(f, p, 0.69314718f);
    p = fmaf(f, p, 1.0f);
    return __int_as_float(__float_as_int(p) + (n << 23));
}

__device__ __forceinline__ void split_bf16(float v, unsigned short& h, unsigned short& l) {
    __nv_bfloat16 hb = __float2bfloat16(v);
    float hf = __bfloat162float(hb);
    __nv_bfloat16 lb = __float2bfloat16(v - hf);
    h = __bfloat16_as_ushort(hb);
    l = __bfloat16_as_ushort(lb);
}

// ---------------------------------------------------------------------------
// Kernel 1: fused QKV projection (fp32 SIMT GEMM), epilogue writes bf16 hi/lo.
// Q,K row-major [tok][64]; V transposed [b][d][T].
// ---------------------------------------------------------------------------
__global__ __launch_bounds__(256) void qkv_kernel(
    const float* __restrict__ X,
    const float* __restrict__ Wq, const float* __restrict__ bq,
    const float* __restrict__ Wk, const float* __restrict__ bk,
    const float* __restrict__ Wv, const float* __restrict__ bv)
{
    __shared__ float Xt[32 * 68];
    __shared__ float Wt[32 * 68];

    const int m0    = blockIdx.x * 64;
    const int which = blockIdx.y;

    const float* W    = (which == 0) ? Wq : (which == 1) ? Wk : Wv;
    const float* bias = (which == 0) ? bq : (which == 1) ? bk : bv;

    const int tid = threadIdx.x;
    const int tx  = tid & 15;
    const int ty  = tid >> 4;

    float acc[4][4];
    #pragma unroll
    for (int i = 0; i < 4; i++)
        #pragma unroll
        for (int j = 0; j < 4; j++) acc[i][j] = 0.f;

    for (int kb = 0; kb < DEMB; kb += 32) {
        __syncthreads();
        #pragma unroll
        for (int it = 0; it < 8; it++) {
            int e  = tid + it * 256;
            int r  = e >> 5;
            int kk = e & 31;
            Xt[kk * 68 + r] = X[(size_t)(m0 + r) * DEMB + kb + kk];
        }
        #pragma unroll
        for (int it = 0; it < 8; it++) {
            int e  = tid + it * 256;
            int c  = e >> 5;
            int kk = e & 31;
            Wt[kk * 68 + c] = W[(size_t)c * DEMB + kb + kk];
        }
        __syncthreads();

        #pragma unroll 8
        for (int kk = 0; kk < 32; kk++) {
            float4 a  = *(const float4*)(Xt + kk * 68 + 4 * ty);
            float4 bb = *(const float4*)(Wt + kk * 68 + 4 * tx);
            const float* ap = (const float*)&a;
            const float* bp = (const float*)&bb;
            #pragma unroll
            for (int i = 0; i < 4; i++)
                #pragma unroll
                for (int j = 0; j < 4; j++)
                    acc[i][j] += ap[i] * bp[j];
        }
    }

    float4 bb4 = *(const float4*)(bias + 4 * tx);
    const float* bp = (const float*)&bb4;

    if (which < 2) {
        __nv_bfloat16* Ch = (which == 0) ? g_Qh : g_Kh;
        __nv_bfloat16* Cl = (which == 0) ? g_Ql : g_Kl;
        #pragma unroll
        for (int i = 0; i < 4; i++) {
            int row = m0 + 4 * ty + i;
            unsigned short h[4], l[4];
            #pragma unroll
            for (int j = 0; j < 4; j++)
                split_bf16(acc[i][j] + bp[j], h[j], l[j]);
            uint2 hv = make_uint2((uint32_t)h[0] | ((uint32_t)h[1] << 16),
                                  (uint32_t)h[2] | ((uint32_t)h[3] << 16));
            uint2 lv = make_uint2((uint32_t)l[0] | ((uint32_t)l[1] << 16),
                                  (uint32_t)l[2] | ((uint32_t)l[3] << 16));
            *(uint2*)(Ch + (size_t)row * DH + 4 * tx) = hv;
            *(uint2*)(Cl + (size_t)row * DH + 4 * tx) = lv;
        }
    } else {
        // V transposed: g_Vt[b][d][t]
        int bb = m0 >> 12;
        int t0 = (m0 & 4095) + 4 * ty;
        #pragma unroll
        for (int i = 0; i < 4; i++) {
            #pragma unroll
            for (int j = 0; j < 4; j++) {
                unsigned short h, l;
                split_bf16(acc[i][j] + bp[j], h, l);
                size_t idx = ((size_t)bb * DH + 4 * tx + j) * TSEQ + t0 + i;
                g_Vth[idx] = __ushort_as_bfloat16(h);
                g_Vtl[idx] = __ushort_as_bfloat16(l);
            }
        }
    }
}

// ---------------------------------------------------------------------------
// Kernel 2: HMMA (mma.sync bf16) flash attention with bf16 error compensation
// and FMA-pipe polynomial exp. M=64 q-rows per tile, N=64 kv per iteration.
// 128 threads = 4 warps, each warp owns 16 q-rows. Each CTA processes the
// q-tile pair (pr, 63-pr) so every CTA does exactly 65 kv iterations.
// ---------------------------------------------------------------------------
#define SM_QH 0
#define SM_QL 8192
#define SM_KH 16384
#define SM_KL 24576
#define SM_VH 32768
#define SM_VL 40960
#define SMEM_ATTN 49152

__global__ __launch_bounds__(128) void attn_mma_kernel(float* __restrict__ Out)
{
    extern __shared__ char smc[];
    const uint32_t smb = smem_u32(smc);

    const int tid  = threadIdx.x;
    const int w    = tid >> 5;
    const int lane = tid & 31;
    const int g    = lane >> 2;     // group id (row within 8)
    const int tq   = lane & 3;      // thread-in-group (col pair)
    const int b    = blockIdx.x & 3;
    const int pr   = blockIdx.x >> 2;   // 0..31

    #pragma unroll
    for (int half = 0; half < 2; half++) {
        const int qt = half ? (63 - pr) : pr;
        const int q0 = qt * 64;

        __syncthreads();
        // ---- load Q tile (hi/lo) into swizzled smem ----
        {
            const uint4* sqh = (const uint4*)(g_Qh + ((size_t)b * TSEQ + q0) * DH);
            const uint4* sql = (const uint4*)(g_Ql + ((size_t)b * TSEQ + q0) * DH);
            #pragma unroll
            for (int t = 0; t < 4; t++) {
                int e = tid + t * 128;          // 0..511 uint4
                uint32_t bo = (uint32_t)e * 16;
                *(uint4*)(smc + SM_QH + SWZ(bo)) = sqh[e];
                *(uint4*)(smc + SM_QL + SWZ(bo)) = sql[e];
            }
        }
        __syncthreads();

        // ---- ldmatrix Q fragments (persist across kv loop) ----
        uint32_t qh[4][4], ql[4][4];
        {
            int arow = 16 * w + (lane & 7) + ((lane & 8) ? 8 : 0);
            int kh8  = (lane >> 4) & 1;
            #pragma unroll
            for (int s = 0; s < 4; s++) {
                uint32_t off = SWZ((uint32_t)(arow * 128 + s * 32 + kh8 * 16));
                LDSM_X4(qh[s], smb + SM_QH + off);
                LDSM_X4(ql[s], smb + SM_QL + off);
            }
        }

        float O[8][4];
        #pragma unroll
        for (int n = 0; n < 8; n++)
            #pragma unroll
            for (int e = 0; e < 4; e++) O[n][e] = 0.f;
        float m0r = -1e30f, m1r = -1e30f, l0 = 0.f, l1 = 0.f;

        for (int kt = 0; kt <= qt; kt++) {
            const int k0 = kt * 64;
            __syncthreads();   // prior iter ldsm reads done

            // ---- load K (hi/lo) and V^T (hi/lo) tiles ----
            {
                const uint4* skh = (const uint4*)(g_Kh + ((size_t)b * TSEQ + k0) * DH);
                const uint4* skl = (const uint4*)(g_Kl + ((size_t)b * TSEQ + k0) * DH);
                #pragma unroll
                for (int t = 0; t < 4; t++) {
                    int e = tid + t * 128;
                    uint32_t bo = (uint32_t)e * 16;
                    *(uint4*)(smc + SM_KH + SWZ(bo)) = skh[e];
                    *(uint4*)(smc + SM_KL + SWZ(bo)) = skl[e];
                }
                const __nv_bfloat16* gvh = g_Vth + (size_t)b * DH * TSEQ;
                const __nv_bfloat16* gvl = g_Vtl + (size_t)b * DH * TSEQ;
                #pragma unroll
                for (int t = 0; t < 4; t++) {
                    int e   = tid + t * 128;
                    int row = e >> 3;           // d
                    int ch  = e & 7;
                    uint32_t bo = (uint32_t)e * 16;
                    *(uint4*)(smc + SM_VH + SWZ(bo)) =
                        *(const uint4*)(gvh + (size_t)row * TSEQ + k0 + ch * 8);
                    *(uint4*)(smc + SM_VL + SWZ(bo)) =
                        *(const uint4*)(gvl + (size_t)row * TSEQ + k0 + ch * 8);
                }
            }
            __syncthreads();

            // ---- S = Q K^T with error compensation ----
            float C[8][4];
            #pragma unroll
            for (int j = 0; j < 8; j++)
                #pragma unroll
                for (int e = 0; e < 4; e++) C[j][e] = 0.f;

            {
                int brow = lane & 7;
                int bh8  = (lane >> 3) & 1;
                #pragma unroll
                for (int j = 0; j < 8; j++) {
                    #pragma unroll
                    for (int s = 0; s < 4; s++) {
                        uint32_t off = SWZ((uint32_t)((8 * j + brow) * 128 + s * 32 + bh8 * 16));
                        uint32_t bh[2], bl[2];
                        LDSM_X2(bh, smb + SM_KH + off);
                        LDSM_X2(bl, smb + SM_KL + off);
                        mma_bf16(C[j], qh[s], bh);
                        mma_bf16(C[j], ql[s], bh);
                        mma_bf16(C[j], qh[s], bl);
                    }
                }
            }

            // ---- causal mask (diagonal tile only) ----
            if (kt == qt) {
                int r0l = 16 * w + g;
                int r1l = r0l + 8;
                #pragma unroll
                for (int j = 0; j < 8; j++) {
                    int col = 8 * j + 2 * tq;
                    if (col     > r0l) C[j][0] = -1e30f;
                    if (col + 1 > r0l) C[j][1] = -1e30f;
                    if (col     > r1l) C[j][2] = -1e30f;
                    if (col + 1 > r1l) C[j][3] = -1e30f;
                }
            }

            // ---- online softmax (poly exp on fma pipe) ----
            float mx0 = -1e30f, mx1 = -1e30f;
            #pragma unroll
            for (int j = 0; j < 8; j++) {
                mx0 = fmaxf(mx0, fmaxf(C[j][0], C[j][1]));
                mx1 = fmaxf(mx1, fmaxf(C[j][2], C[j][3]));
            }
            mx0 = fmaxf(mx0, __shfl_xor_sync(0xffffffffu, mx0, 1));
            mx0 = fmaxf(mx0, __shfl_xor_sync(0xffffffffu, mx0, 2));
            mx1 = fmaxf(mx1, __shfl_xor_sync(0xffffffffu, mx1, 1));
            mx1 = fmaxf(mx1, __shfl_xor_sync(0xffffffffu, mx1, 2));

            float mn0 = fmaxf(m0r, mx0), mn1 = fmaxf(m1r, mx1);
            float scl0 = exp2ap((m0r - mn0) * L2E);
            float scl1 = exp2ap((m1r - mn1) * L2E);
            m0r = mn0; m1r = mn1;
            float base0 = mn0 * L2E, base1 = mn1 * L2E;

            float s0 = 0.f, s1 = 0.f;
            uint32_t ph[4][4], pl[4][4];
            #pragma unroll
            for (int j = 0; j < 8; j++) {
                float p00 = exp2ap(fmaf(C[j][0], L2E, -base0));
                float p01 = exp2ap(fmaf(C[j][1], L2E, -base0));
                float p10 = exp2ap(fmaf(C[j][2], L2E, -base1));
                float p11 = exp2ap(fmaf(C[j][3], L2E, -base1));
                s0 += p00 + p01;
                s1 += p10 + p11;

                __nv_bfloat162 H0 = __floats2bfloat162_rn(p00, p01);
                __nv_bfloat162 H1 = __floats2bfloat162_rn(p10, p11);
                __nv_bfloat162 L0 = __floats2bfloat162_rn(p00 - __bfloat162float(H0.x),
                                                          p01 - __bfloat162float(H0.y));
                __nv_bfloat162 L1 = __floats2bfloat162_rn(p10 - __bfloat162float(H1.x),
                                                          p11 - __bfloat162float(H1.y));
                int sp = j >> 1;           // k16 block
                int rlo = (j & 1) * 2;     // regs 0,1 (k low8) or 2,3 (k high8)
                ph[sp][rlo]     = *(uint32_t*)&H0;
                ph[sp][rlo + 1] = *(uint32_t*)&H1;
                pl[sp][rlo]     = *(uint32_t*)&L0;
                pl[sp][rlo + 1] = *(uint32_t*)&L1;
            }
            s0 += __shfl_xor_sync(0xffffffffu, s0, 1);
            s0 += __shfl_xor_sync(0xffffffffu, s0, 2);
            s1 += __shfl_xor_sync(0xffffffffu, s1, 1);
            s1 += __shfl_xor_sync(0xffffffffu, s1, 2);
            l0 = l0 * scl0 + s0;
            l1 = l1 * scl1 + s1;

            // rescale O
            #pragma unroll
            for (int n = 0; n < 8; n++) {
                O[n][0] *= scl0; O[n][1] *= scl0;
                O[n][2] *= scl1; O[n][3] *= scl1;
            }

            // ---- O += P V with error compensation ----
            {
                int brow = lane & 7;
                int bh8  = (lane >> 3) & 1;
                #pragma unroll
                for (int n = 0; n < 8; n++) {
                    #pragma unroll
                    for (int s = 0; s < 4; s++) {
                        uint32_t off = SWZ((uint32_t)((8 * n + brow) * 128 + s * 32 + bh8 * 16));
                        uint32_t vh[2], vl[2];
                        LDSM_X2(vh, smb + SM_VH + off);
                        LDSM_X2(vl, smb + SM_VL + off);
                        mma_bf16(O[n], ph[s], vh);
                        mma_bf16(O[n], pl[s], vh);
                        mma_bf16(O[n], ph[s], vl);
                    }
                }
            }
        }

        // ---- epilogue: out = O * sqrt(64) / l ----
        {
            float inv0 = 8.0f / l0, inv1 = 8.0f / l1;
            float* dst = Out + ((size_t)b * TSEQ + q0) * DH;
            int r0 = 16 * w + g, r1 = r0 + 8;
            #pragma unroll
            for (int n = 0; n < 8; n++) {
                int col = 8 * n + 2 * tq;
                *(float2*)(dst + (size_t)r0 * DH + col) =
                    make_float2(O[n][0] * inv0, O[n][1] * inv0);
                *(float2*)(dst + (size_t)r1 * DH + col) =
                    make_float2(O[n][2] * inv1, O[n][3] * inv1);
            }
        }
    }
}

// ---------------------------------------------------------------------------
// Launch: inputs per metadata order: x, Wq_w, Wq_b, Wk_w, Wk_b, Wv_w, Wv_b
// ---------------------------------------------------------------------------
extern "C" void kernel_launch(void* const* d_in, const int* in_sizes, int n_in,
                              void* d_out, int out_size)
{
    const float* x  = (const float*)d_in[0];
    const float* Wq = (const float*)d_in[1];
    const float* bq = (const float*)d_in[2];
    const float* Wk = (const float*)d_in[3];
    const float* bk = (const float*)d_in[4];
    const float* Wv = (const float*)d_in[5];
    const float* bv = (const float*)d_in[6];
    float* out = (float*)d_out;

    qkv_kernel<<<dim3(256, 3), 256>>>(x, Wq, bq, Wk, bk, Wv, bv);

    cudaFuncSetAttribute(attn_mma_kernel,
                         cudaFuncAttributeMaxDynamicSharedMemorySize,
                         SMEM_ATTN);
    attn_mma_kernel<<<128, 128, SMEM_ATTN>>>(out);
}

// round 4
// speedup vs baseline: 3.4352x; 2.2070x over previous
#include <cuda_runtime.h>
#include <cuda_bf16.h>
#include <stdint.h>

// Problem constants
#define BATCH   4
#define TSEQ    4096
#define DEMB    512
#define DH      64
#define NTOK    (BATCH * TSEQ)   // 16384

// ---------------------------------------------------------------------------
// Global scratch
// ---------------------------------------------------------------------------
__device__ __nv_bfloat16 g_Qh[NTOK * DH];
__device__ __nv_bfloat16 g_Ql[NTOK * DH];
__device__ __nv_bfloat16 g_Kh[NTOK * DH];
__device__ __nv_bfloat16 g_Kl[NTOK * DH];
__device__ __nv_bfloat16 g_Vh[NTOK * DH];   // row-major now
__device__ __nv_bfloat16 g_Vl[NTOK * DH];

// Split-KV partials: slot = ((b*64 + qt)*4 + chunk)
#define NSLOT (BATCH * 64 * 4)
__device__ float g_pO[NSLOT * 64 * 64];   // 16.8 MB
__device__ float g_pm[NSLOT * 64];
__device__ float g_pl[NSLOT * 64];

// ---------------------------------------------------------------------------
// Helpers
// ---------------------------------------------------------------------------
__device__ __forceinline__ uint32_t smem_u32(const void* p) {
    uint32_t a;
    asm("{ .reg .u64 t; cvta.to.shared.u64 t, %1; cvt.u32.u64 %0, t; }"
        : "=r"(a) : "l"(p));
    return a;
}

#define SWZ(o) ((o) ^ (((o) >> 3) & 0x70))

#define LDSM_X4(r, addr) \
    asm volatile("ldmatrix.sync.aligned.m8n8.x4.shared.b16 {%0,%1,%2,%3}, [%4];" \
        : "=r"((r)[0]), "=r"((r)[1]), "=r"((r)[2]), "=r"((r)[3]) : "r"(addr))
#define LDSM_X2(r, addr) \
    asm volatile("ldmatrix.sync.aligned.m8n8.x2.shared.b16 {%0,%1}, [%2];" \
        : "=r"((r)[0]), "=r"((r)[1]) : "r"(addr))
#define LDSM_X2_T(r, addr) \
    asm volatile("ldmatrix.sync.aligned.m8n8.x2.trans.shared.b16 {%0,%1}, [%2];" \
        : "=r"((r)[0]), "=r"((r)[1]) : "r"(addr))

// m16n8k16 bf16 -> f32 accumulate (HMMA)
__device__ __forceinline__ void mma_bf16(float* c, const uint32_t* a, const uint32_t* b) {
    asm volatile(
        "mma.sync.aligned.m16n8k16.row.col.f32.bf16.bf16.f32 "
        "{%0,%1,%2,%3}, {%4,%5,%6,%7}, {%8,%9}, {%0,%1,%2,%3};"
        : "+f"(c[0]), "+f"(c[1]), "+f"(c[2]), "+f"(c[3])
        : "r"(a[0]), "r"(a[1]), "r"(a[2]), "r"(a[3]), "r"(b[0]), "r"(b[1]));
}

#define L2E 1.44269504088896f

// Fast exp2 on the FMA/ALU pipes (no MUFU).
__device__ __forceinline__ float exp2ap(float t) {
    t = fmaxf(t, -126.0f);
    float r = t + 12582912.0f;
    int   n = __float_as_int(r) - 0x4B400000;
    float f = t - (r - 12582912.0f);
    float p = fmaf(f, 0.00961813f, 0.05550411f);
    p = fmaf(f, p, 0.24022651f);
    p = fmaf(f, p, 0.69314718f);
    p = fmaf(f, p, 1.0f);
    return __int_as_float(__float_as_int(p) + (n << 23));
}

__device__ __forceinline__ void split_bf16(float v, unsigned short& h, unsigned short& l) {
    __nv_bfloat16 hb = __float2bfloat16(v);
    float hf = __bfloat162float(hb);
    __nv_bfloat16 lb = __float2bfloat16(v - hf);
    h = __bfloat16_as_ushort(hb);
    l = __bfloat16_as_ushort(lb);
}

// Pack 4 floats into hi uint2 / lo uint2 bf16 pairs
__device__ __forceinline__ void pack4(const float4 v, uint2& h, uint2& l) {
    unsigned short h0, l0, h1, l1, h2, l2, h3, l3;
    split_bf16(v.x, h0, l0); split_bf16(v.y, h1, l1);
    split_bf16(v.z, h2, l2); split_bf16(v.w, h3, l3);
    h = make_uint2((uint32_t)h0 | ((uint32_t)h1 << 16),
                   (uint32_t)h2 | ((uint32_t)h3 << 16));
    l = make_uint2((uint32_t)l0 | ((uint32_t)l1 << 16),
                   (uint32_t)l2 | ((uint32_t)l3 << 16));
}

// ---------------------------------------------------------------------------
// Kernel 1: fused QKV projection via HMMA with bf16 error compensation.
// C = X @ W^T + b.  One CTA = 64 tokens x one of {Q,K,V}. 128 threads.
// Inner loop over 8 k-chunks of 64; X/W tiles converted fp32->bf16 h/l in smem.
// ---------------------------------------------------------------------------
#define QK_XH 0
#define QK_XL 8192
#define QK_WH 16384
#define QK_WL 24576

__global__ __launch_bounds__(128) void qkv_mma_kernel(
    const float* __restrict__ X,
    const float* __restrict__ Wq, const float* __restrict__ bq,
    const float* __restrict__ Wk, const float* __restrict__ bk,
    const float* __restrict__ Wv, const float* __restrict__ bv)
{
    __shared__ char smc[32768];
    const uint32_t smb = smem_u32(smc);

    const int m0    = blockIdx.x * 64;
    const int which = blockIdx.y;

    const float* W    = (which == 0) ? Wq : (which == 1) ? Wk : Wv;
    const float* bias = (which == 0) ? bq : (which == 1) ? bk : bv;
    __nv_bfloat16* Ch = (which == 0) ? g_Qh : (which == 1) ? g_Kh : g_Vh;
    __nv_bfloat16* Cl = (which == 0) ? g_Ql : (which == 1) ? g_Kl : g_Vl;

    const int tid  = threadIdx.x;
    const int w    = tid >> 5;
    const int lane = tid & 31;
    const int g    = lane >> 2;
    const int tq   = lane & 3;

    float c[8][4];
    #pragma unroll
    for (int nb = 0; nb < 8; nb++)
        #pragma unroll
        for (int e = 0; e < 4; e++) c[nb][e] = 0.f;

    const int arow = 16 * w + (lane & 15);
    const int kh8  = (lane >> 4) & 1;
    const int brow = lane & 7;
    const int bh8  = (lane >> 3) & 1;

    for (int kc = 0; kc < 8; kc++) {
        __syncthreads();
        // Load + split X tile [64 tok][64 k] and W tile [64 out][64 k]
        #pragma unroll
        for (int it = 0; it < 8; it++) {
            int e   = tid + it * 128;     // 0..1023 float4
            int row = e >> 4;
            int c4  = e & 15;
            float4 xv = *(const float4*)(X + (size_t)(m0 + row) * DEMB + kc * 64 + 4 * c4);
            uint2 h, l;
            pack4(xv, h, l);
            uint32_t bo = SWZ((uint32_t)(row * 128 + 8 * c4));
            *(uint2*)(smc + QK_XH + bo) = h;
            *(uint2*)(smc + QK_XL + bo) = l;
            float4 wv = *(const float4*)(W + (size_t)row * DEMB + kc * 64 + 4 * c4);
            pack4(wv, h, l);
            *(uint2*)(smc + QK_WH + bo) = h;
            *(uint2*)(smc + QK_WL + bo) = l;
        }
        __syncthreads();

        uint32_t ah[4][4], al[4][4];
        #pragma unroll
        for (int s = 0; s < 4; s++) {
            uint32_t off = SWZ((uint32_t)(arow * 128 + s * 32 + kh8 * 16));
            LDSM_X4(ah[s], smb + QK_XH + off);
            LDSM_X4(al[s], smb + QK_XL + off);
        }
        #pragma unroll
        for (int nb = 0; nb < 8; nb++) {
            #pragma unroll
            for (int s = 0; s < 4; s++) {
                uint32_t off = SWZ((uint32_t)((8 * nb + brow) * 128 + s * 32 + bh8 * 16));
                uint32_t bh[2], bl[2];
                LDSM_X2(bh, smb + QK_WH + off);
                LDSM_X2(bl, smb + QK_WL + off);
                mma_bf16(c[nb], ah[s], bh);
                mma_bf16(c[nb], al[s], bh);
                mma_bf16(c[nb], ah[s], bl);
            }
        }
    }

    // Epilogue: bias + hi/lo split, row-major stores
    const int r0 = m0 + 16 * w + g;
    const int r1 = r0 + 8;
    #pragma unroll
    for (int nb = 0; nb < 8; nb++) {
        int col = 8 * nb + 2 * tq;
        float b0 = bias[col], b1 = bias[col + 1];
        unsigned short h0, l0, h1, l1;
        split_bf16(c[nb][0] + b0, h0, l0);
        split_bf16(c[nb][1] + b1, h1, l1);
        *(uint32_t*)(Ch + (size_t)r0 * DH + col) = (uint32_t)h0 | ((uint32_t)h1 << 16);
        *(uint32_t*)(Cl + (size_t)r0 * DH + col) = (uint32_t)l0 | ((uint32_t)l1 << 16);
        split_bf16(c[nb][2] + b0, h0, l0);
        split_bf16(c[nb][3] + b1, h1, l1);
        *(uint32_t*)(Ch + (size_t)r1 * DH + col) = (uint32_t)h0 | ((uint32_t)h1 << 16);
        *(uint32_t*)(Cl + (size_t)r1 * DH + col) = (uint32_t)l0 | ((uint32_t)l1 << 16);
    }
}

// ---------------------------------------------------------------------------
// Kernel 2: split-KV HMMA flash attention. One CTA = (b, q-tile of 64 rows,
// kv-chunk of <=16 kv-tiles of 64). 128 threads = 4 warps. Writes partial
// (O, m, l) to gmem; combine kernel merges.
// ---------------------------------------------------------------------------
#define SM_QH 0
#define SM_QL 8192
#define SM_KH 16384
#define SM_KL 24576
#define SM_VH 32768
#define SM_VL 40960
#define SMEM_ATTN 49152

__global__ __launch_bounds__(128) void attn_part_kernel()
{
    extern __shared__ char smc[];
    const uint32_t smb = smem_u32(smc);

    const int tid  = threadIdx.x;
    const int w    = tid >> 5;
    const int lane = tid & 31;
    const int g    = lane >> 2;
    const int tq   = lane & 3;

    // blockIdx -> (b, qt, chunk)
    const int id = blockIdx.x;
    const int b  = id / 160;
    const int r  = id % 160;
    int qt, ch;
    if      (r <  64) { qt = r;              ch = 0; }
    else if (r < 112) { qt = 16 + (r - 64);  ch = 1; }
    else if (r < 144) { qt = 32 + (r - 112); ch = 2; }
    else              { qt = 48 + (r - 144); ch = 3; }
    const int k_lo = 16 * ch;
    const int k_hi = min(qt, 16 * ch + 15);
    const int slot = (b * 64 + qt) * 4 + ch;
    const int q0   = qt * 64;

    // ---- load Q tile (hi/lo) ----
    {
        const uint4* sqh = (const uint4*)(g_Qh + ((size_t)b * TSEQ + q0) * DH);
        const uint4* sql = (const uint4*)(g_Ql + ((size_t)b * TSEQ + q0) * DH);
        #pragma unroll
        for (int t = 0; t < 4; t++) {
            int e = tid + t * 128;
            uint32_t bo = (uint32_t)e * 16;
            *(uint4*)(smc + SM_QH + SWZ(bo)) = sqh[e];
            *(uint4*)(smc + SM_QL + SWZ(bo)) = sql[e];
        }
    }
    __syncthreads();

    // ---- Q fragments (persist) ----
    uint32_t qh[4][4], ql[4][4];
    {
        int arow = 16 * w + (lane & 15);
        int kh8  = (lane >> 4) & 1;
        #pragma unroll
        for (int s = 0; s < 4; s++) {
            uint32_t off = SWZ((uint32_t)(arow * 128 + s * 32 + kh8 * 16));
            LDSM_X4(qh[s], smb + SM_QH + off);
            LDSM_X4(ql[s], smb + SM_QL + off);
        }
    }

    float O[8][4];
    #pragma unroll
    for (int n = 0; n < 8; n++)
        #pragma unroll
        for (int e = 0; e < 4; e++) O[n][e] = 0.f;
    float m0r = -1e30f, m1r = -1e30f, l0 = 0.f, l1 = 0.f;

    const int brow = lane & 7;
    const int bh8  = (lane >> 3) & 1;
    const int vrow = lane & 15;

    for (int kt = k_lo; kt <= k_hi; kt++) {
        const int k0 = kt * 64;
        __syncthreads();

        // ---- load K (hi/lo) and V (hi/lo, row-major) tiles ----
        {
            const uint4* skh = (const uint4*)(g_Kh + ((size_t)b * TSEQ + k0) * DH);
            const uint4* skl = (const uint4*)(g_Kl + ((size_t)b * TSEQ + k0) * DH);
            const uint4* svh = (const uint4*)(g_Vh + ((size_t)b * TSEQ + k0) * DH);
            const uint4* svl = (const uint4*)(g_Vl + ((size_t)b * TSEQ + k0) * DH);
            #pragma unroll
            for (int t = 0; t < 4; t++) {
                int e = tid + t * 128;
                uint32_t bo = SWZ((uint32_t)e * 16);
                *(uint4*)(smc + SM_KH + bo) = skh[e];
                *(uint4*)(smc + SM_KL + bo) = skl[e];
                *(uint4*)(smc + SM_VH + bo) = svh[e];
                *(uint4*)(smc + SM_VL + bo) = svl[e];
            }
        }
        __syncthreads();

        // ---- S = Q K^T (3-term compensation) ----
        float C[8][4];
        #pragma unroll
        for (int j = 0; j < 8; j++)
            #pragma unroll
            for (int e = 0; e < 4; e++) C[j][e] = 0.f;

        #pragma unroll
        for (int j = 0; j < 8; j++) {
            #pragma unroll
            for (int s = 0; s < 4; s++) {
                uint32_t off = SWZ((uint32_t)((8 * j + brow) * 128 + s * 32 + bh8 * 16));
                uint32_t bh[2], bl[2];
                LDSM_X2(bh, smb + SM_KH + off);
                LDSM_X2(bl, smb + SM_KL + off);
                mma_bf16(C[j], qh[s], bh);
                mma_bf16(C[j], ql[s], bh);
                mma_bf16(C[j], qh[s], bl);
            }
        }

        // ---- causal mask (diagonal tile only) ----
        if (kt * 64 + 63 > q0) {          // only possible when kt == qt
            int r0l = 16 * w + g;
            int r1l = r0l + 8;
            #pragma unroll
            for (int j = 0; j < 8; j++) {
                int col = 8 * j + 2 * tq;
                if (col     > r0l) C[j][0] = -1e30f;
                if (col + 1 > r0l) C[j][1] = -1e30f;
                if (col     > r1l) C[j][2] = -1e30f;
                if (col + 1 > r1l) C[j][3] = -1e30f;
            }
        }

        // ---- online softmax ----
        float mx0 = -1e30f, mx1 = -1e30f;
        #pragma unroll
        for (int j = 0; j < 8; j++) {
            mx0 = fmaxf(mx0, fmaxf(C[j][0], C[j][1]));
            mx1 = fmaxf(mx1, fmaxf(C[j][2], C[j][3]));
        }
        mx0 = fmaxf(mx0, __shfl_xor_sync(0xffffffffu, mx0, 1));
        mx0 = fmaxf(mx0, __shfl_xor_sync(0xffffffffu, mx0, 2));
        mx1 = fmaxf(mx1, __shfl_xor_sync(0xffffffffu, mx1, 1));
        mx1 = fmaxf(mx1, __shfl_xor_sync(0xffffffffu, mx1, 2));

        float mn0 = fmaxf(m0r, mx0), mn1 = fmaxf(m1r, mx1);
        float scl0 = exp2ap((m0r - mn0) * L2E);
        float scl1 = exp2ap((m1r - mn1) * L2E);
        m0r = mn0; m1r = mn1;
        float base0 = mn0 * L2E, base1 = mn1 * L2E;

        float s0 = 0.f, s1 = 0.f;
        uint32_t ph[4][4], pl[4][4];
        #pragma unroll
        for (int j = 0; j < 8; j++) {
            float p00 = exp2ap(fmaf(C[j][0], L2E, -base0));
            float p01 = exp2ap(fmaf(C[j][1], L2E, -base0));
            float p10 = exp2ap(fmaf(C[j][2], L2E, -base1));
            float p11 = exp2ap(fmaf(C[j][3], L2E, -base1));
            s0 += p00 + p01;
            s1 += p10 + p11;

            __nv_bfloat162 H0 = __floats2bfloat162_rn(p00, p01);
            __nv_bfloat162 H1 = __floats2bfloat162_rn(p10, p11);
            __nv_bfloat162 L0 = __floats2bfloat162_rn(p00 - __bfloat162float(H0.x),
                                                      p01 - __bfloat162float(H0.y));
            __nv_bfloat162 L1 = __floats2bfloat162_rn(p10 - __bfloat162float(H1.x),
                                                      p11 - __bfloat162float(H1.y));
            int sp  = j >> 1;
            int rlo = (j & 1) * 2;
            ph[sp][rlo]     = *(uint32_t*)&H0;
            ph[sp][rlo + 1] = *(uint32_t*)&H1;
            pl[sp][rlo]     = *(uint32_t*)&L0;
            pl[sp][rlo + 1] = *(uint32_t*)&L1;
        }
        s0 += __shfl_xor_sync(0xffffffffu, s0, 1);
        s0 += __shfl_xor_sync(0xffffffffu, s0, 2);
        s1 += __shfl_xor_sync(0xffffffffu, s1, 1);
        s1 += __shfl_xor_sync(0xffffffffu, s1, 2);
        l0 = l0 * scl0 + s0;
        l1 = l1 * scl1 + s1;

        #pragma unroll
        for (int n = 0; n < 8; n++) {
            O[n][0] *= scl0; O[n][1] *= scl0;
            O[n][2] *= scl1; O[n][3] *= scl1;
        }

        // ---- O += P V (V row-major, ldmatrix.trans) ----
        #pragma unroll
        for (int n = 0; n < 8; n++) {
            #pragma unroll
            for (int s = 0; s < 4; s++) {
                uint32_t off = SWZ((uint32_t)((16 * s + vrow) * 128 + n * 16));
                uint32_t vh[2], vl[2];
                LDSM_X2_T(vh, smb + SM_VH + off);
                LDSM_X2_T(vl, smb + SM_VL + off);
                mma_bf16(O[n], ph[s], vh);
                mma_bf16(O[n], pl[s], vh);
                mma_bf16(O[n], ph[s], vl);
            }
        }
    }

    // ---- write partials ----
    {
        float* pO = g_pO + (size_t)slot * 64 * 64;
        int r0l = 16 * w + g;
        int r1l = r0l + 8;
        #pragma unroll
        for (int n = 0; n < 8; n++) {
            int col = 8 * n + 2 * tq;
            *(float2*)(pO + r0l * 64 + col) = make_float2(O[n][0], O[n][1]);
            *(float2*)(pO + r1l * 64 + col) = make_float2(O[n][2], O[n][3]);
        }
        if (tq == 0) {
            g_pm[slot * 64 + r0l] = m0r;
            g_pm[slot * 64 + r1l] = m1r;
            g_pl[slot * 64 + r0l] = l0;
            g_pl[slot * 64 + r1l] = l1;
        }
    }
}

// ---------------------------------------------------------------------------
// Kernel 3: combine split-KV partials. One CTA per (b, qt). 128 threads.
// ---------------------------------------------------------------------------
__global__ __launch_bounds__(128) void attn_combine_kernel(float* __restrict__ Out)
{
    const int blk = blockIdx.x;
    const int b   = blk >> 6;
    const int qt  = blk & 63;
    const int t   = threadIdx.x;
    const int row = t >> 1;
    const int hf  = t & 1;

    const int nc    = (qt >> 4) + 1;
    const int sbase = (b * 64 + qt) * 4;

    float mv[4], lv[4];
    float m = -1e30f;
    for (int c = 0; c < nc; c++) {
        mv[c] = g_pm[(sbase + c) * 64 + row];
        lv[c] = g_pl[(sbase + c) * 64 + row];
        m = fmaxf(m, mv[c]);
    }
    float l = 0.f;
    float wc[4];
    for (int c = 0; c < nc; c++) {
        wc[c] = exp2ap((mv[c] - m) * L2E);
        l += wc[c] * lv[c];
    }
    float inv = 8.0f / l;

    float* dst = Out + ((size_t)b * TSEQ + (size_t)qt * 64 + row) * DH + 32 * hf;
    #pragma unroll
    for (int j = 0; j < 8; j++) {
        int col = 32 * hf + 4 * j;
        float4 acc = make_float4(0.f, 0.f, 0.f, 0.f);
        for (int c = 0; c < nc; c++) {
            const float4 v = *(const float4*)(g_pO + (size_t)(sbase + c) * 4096 + row * 64 + col);
            acc.x += wc[c] * v.x; acc.y += wc[c] * v.y;
            acc.z += wc[c] * v.z; acc.w += wc[c] * v.w;
        }
        *(float4*)(dst + 4 * j) = make_float4(acc.x * inv, acc.y * inv,
                                              acc.z * inv, acc.w * inv);
    }
}

// ---------------------------------------------------------------------------
// Launch: inputs per metadata order: x, Wq_w, Wq_b, Wk_w, Wk_b, Wv_w, Wv_b
// ---------------------------------------------------------------------------
extern "C" void kernel_launch(void* const* d_in, const int* in_sizes, int n_in,
                              void* d_out, int out_size)
{
    const float* x  = (const float*)d_in[0];
    const float* Wq = (const float*)d_in[1];
    const float* bq = (const float*)d_in[2];
    const float* Wk = (const float*)d_in[3];
    const float* bk = (const float*)d_in[4];
    const float* Wv = (const float*)d_in[5];
    const float* bv = (const float*)d_in[6];
    float* out = (float*)d_out;

    qkv_mma_kernel<<<dim3(256, 3), 128>>>(x, Wq, bq, Wk, bk, Wv, bv);

    cudaFuncSetAttribute(attn_part_kernel,
                         cudaFuncAttributeMaxDynamicSharedMemorySize,
                         SMEM_ATTN);
    attn_part_kernel<<<640, 128, SMEM_ATTN>>>();

    attn_combine_kernel<<<256, 128>>>(out);
}

// round 5
// speedup vs baseline: 3.4478x; 1.0037x over previous
#include <cuda_runtime.h>
#include <cuda_bf16.h>
#include <stdint.h>

// Problem constants
#define BATCH   4
#define TSEQ    4096
#define DEMB    512
#define DH      64
#define NTOK    (BATCH * TSEQ)   // 16384

// ---------------------------------------------------------------------------
// Global scratch
// ---------------------------------------------------------------------------
__device__ __nv_bfloat16 g_Qh[NTOK * DH];
__device__ __nv_bfloat16 g_Ql[NTOK * DH];
__device__ __nv_bfloat16 g_Kh[NTOK * DH];
__device__ __nv_bfloat16 g_Kl[NTOK * DH];
__device__ __nv_bfloat16 g_Vh[NTOK * DH];
__device__ __nv_bfloat16 g_Vl[NTOK * DH];

// Pre-split weights: rows 0-63 = Wq, 64-127 = Wk, 128-191 = Wv ([192][512])
__device__ __nv_bfloat16 g_Wsh[192 * DEMB];
__device__ __nv_bfloat16 g_Wsl[192 * DEMB];

// Split-KV partials: slot = ((b*64 + qt)*4 + chunk)
#define NSLOT (BATCH * 64 * 4)
__device__ float g_pO[NSLOT * 64 * 64];
__device__ float g_pm[NSLOT * 64];
__device__ float g_pl[NSLOT * 64];

// ---------------------------------------------------------------------------
// Helpers
// ---------------------------------------------------------------------------
__device__ __forceinline__ uint32_t smem_u32(const void* p) {
    uint32_t a;
    asm("{ .reg .u64 t; cvta.to.shared.u64 t, %1; cvt.u32.u64 %0, t; }"
        : "=r"(a) : "l"(p));
    return a;
}

#define SWZ(o) ((o) ^ (((o) >> 3) & 0x70))

#define LDSM_X4(r, addr) \
    asm volatile("ldmatrix.sync.aligned.m8n8.x4.shared.b16 {%0,%1,%2,%3}, [%4];" \
        : "=r"((r)[0]), "=r"((r)[1]), "=r"((r)[2]), "=r"((r)[3]) : "r"(addr))
#define LDSM_X2(r, addr) \
    asm volatile("ldmatrix.sync.aligned.m8n8.x2.shared.b16 {%0,%1}, [%2];" \
        : "=r"((r)[0]), "=r"((r)[1]) : "r"(addr))
#define LDSM_X2_T(r, addr) \
    asm volatile("ldmatrix.sync.aligned.m8n8.x2.trans.shared.b16 {%0,%1}, [%2];" \
        : "=r"((r)[0]), "=r"((r)[1]) : "r"(addr))

#define CP_ASYNC16(dst, src) \
    asm volatile("cp.async.cg.shared.global [%0], [%1], 16;" \
        :: "r"(dst), "l"(src))
#define CP_COMMIT()  asm volatile("cp.async.commit_group;" ::: "memory")
#define CP_WAIT(n)   asm volatile("cp.async.wait_group %0;" :: "n"(n) : "memory")

// m16n8k16 bf16 -> f32 accumulate (HMMA)
__device__ __forceinline__ void mma_bf16(float* c, const uint32_t* a, const uint32_t* b) {
    asm volatile(
        "mma.sync.aligned.m16n8k16.row.col.f32.bf16.bf16.f32 "
        "{%0,%1,%2,%3}, {%4,%5,%6,%7}, {%8,%9}, {%0,%1,%2,%3};"
        : "+f"(c[0]), "+f"(c[1]), "+f"(c[2]), "+f"(c[3])
        : "r"(a[0]), "r"(a[1]), "r"(a[2]), "r"(a[3]), "r"(b[0]), "r"(b[1]));
}

#define L2E 1.44269504088896f

// Fast exp2 on the FMA/ALU pipes (no MUFU).
__device__ __forceinline__ float exp2ap(float t) {
    t = fmaxf(t, -126.0f);
    float r = t + 12582912.0f;
    int   n = __float_as_int(r) - 0x4B400000;
    float f = t - (r - 12582912.0f);
    float p = fmaf(f, 0.00961813f, 0.05550411f);
    p = fmaf(f, p, 0.24022651f);
    p = fmaf(f, p, 0.69314718f);
    p = fmaf(f, p, 1.0f);
    return __int_as_float(__float_as_int(p) + (n << 23));
}

__device__ __forceinline__ void split_bf16(float v, unsigned short& h, unsigned short& l) {
    __nv_bfloat16 hb = __float2bfloat16(v);
    float hf = __bfloat162float(hb);
    __nv_bfloat16 lb = __float2bfloat16(v - hf);
    h = __bfloat16_as_ushort(hb);
    l = __bfloat16_as_ushort(lb);
}

__device__ __forceinline__ void pack4(const float4 v, uint2& h, uint2& l) {
    unsigned short h0, l0, h1, l1, h2, l2, h3, l3;
    split_bf16(v.x, h0, l0); split_bf16(v.y, h1, l1);
    split_bf16(v.z, h2, l2); split_bf16(v.w, h3, l3);
    h = make_uint2((uint32_t)h0 | ((uint32_t)h1 << 16),
                   (uint32_t)h2 | ((uint32_t)h3 << 16));
    l = make_uint2((uint32_t)l0 | ((uint32_t)l1 << 16),
                   (uint32_t)l2 | ((uint32_t)l3 << 16));
}

// ---------------------------------------------------------------------------
// Kernel 0: pre-split weights into bf16 hi/lo.
// ---------------------------------------------------------------------------
__global__ __launch_bounds__(256) void wsplit_kernel(
    const float* __restrict__ Wq, const float* __restrict__ Wk,
    const float* __restrict__ Wv)
{
    int idx = blockIdx.x * 256 + threadIdx.x;      // 0 .. 98303
    int row = idx >> 9;
    int col = idx & 511;
    const float* W = (row < 64) ? Wq : (row < 128) ? Wk : Wv;
    int r = row & 63;
    float v = W[(size_t)r * DEMB + col];
    unsigned short h, l;
    split_bf16(v, h, l);
    g_Wsh[idx] = __ushort_as_bfloat16(h);
    g_Wsl[idx] = __ushort_as_bfloat16(l);
}

// ---------------------------------------------------------------------------
// Kernel 1: fused QKV projection via HMMA. One CTA = 128 tokens x ALL 192
// outputs (Q|K|V). 256 threads = 8 warps, each warp 16 token rows.
// X loaded+split once per CTA; weights cp.async'd as pre-split bf16.
// ---------------------------------------------------------------------------
#define QF_XH 0
#define QF_XL 16384
#define QF_WH 32768
#define QF_WL 57344
#define QF_SMEM 81920

__global__ __launch_bounds__(256) void qkv_fused_kernel(
    const float* __restrict__ X,
    const float* __restrict__ bq, const float* __restrict__ bk,
    const float* __restrict__ bv)
{
    extern __shared__ char smc[];
    const uint32_t smb = smem_u32(smc);

    const int m0   = blockIdx.x * 128;
    const int tid  = threadIdx.x;
    const int w    = tid >> 5;
    const int lane = tid & 31;
    const int g    = lane >> 2;
    const int tq   = lane & 3;

    float c[24][4];
    #pragma unroll
    for (int nb = 0; nb < 24; nb++)
        #pragma unroll
        for (int e = 0; e < 4; e++) c[nb][e] = 0.f;

    const int arow = 16 * w + (lane & 15);
    const int kh8  = (lane >> 4) & 1;
    const int brow = lane & 7;
    const int bh8  = (lane >> 3) & 1;

    for (int kc = 0; kc < 8; kc++) {
        __syncthreads();   // prev compute done before overwriting tiles

        // Prefetch W tiles [192][64] bf16 h/l via cp.async
        #pragma unroll
        for (int it = 0; it < 6; it++) {
            int e   = tid + it * 256;        // 0..1535
            int row = e >> 3;
            int c8  = e & 7;
            uint32_t dsto = SWZ((uint32_t)(row * 128 + 16 * c8));
            const char* srch = (const char*)(g_Wsh + (size_t)row * DEMB + kc * 64 + 8 * c8);
            const char* srcl = (const char*)(g_Wsl + (size_t)row * DEMB + kc * 64 + 8 * c8);
            CP_ASYNC16(smb + QF_WH + dsto, srch);
            CP_ASYNC16(smb + QF_WL + dsto, srcl);
        }
        CP_COMMIT();

        // Load + split X tile [128 tok][64 k]
        #pragma unroll
        for (int it = 0; it < 8; it++) {
            int e   = tid + it * 256;        // 0..2047 float4
            int row = e >> 4;
            int c4  = e & 15;
            float4 xv = *(const float4*)(X + (size_t)(m0 + row) * DEMB + kc * 64 + 4 * c4);
            uint2 h, l;
            pack4(xv, h, l);
            uint32_t bo = SWZ((uint32_t)(row * 128 + 8 * c4));
            *(uint2*)(smc + QF_XH + bo) = h;
            *(uint2*)(smc + QF_XL + bo) = l;
        }
        CP_WAIT(0);
        __syncthreads();

        uint32_t ah[4][4], al[4][4];
        #pragma unroll
        for (int s = 0; s < 4; s++) {
            uint32_t off = SWZ((uint32_t)(arow * 128 + s * 32 + kh8 * 16));
            LDSM_X4(ah[s], smb + QF_XH + off);
            LDSM_X4(al[s], smb + QF_XL + off);
        }
        #pragma unroll
        for (int nb = 0; nb < 24; nb++) {
            #pragma unroll
            for (int s = 0; s < 4; s++) {
                uint32_t off = SWZ((uint32_t)((8 * nb + brow) * 128 + s * 32 + bh8 * 16));
                uint32_t bh[2], bl[2];
                LDSM_X2(bh, smb + QF_WH + off);
                LDSM_X2(bl, smb + QF_WL + off);
                mma_bf16(c[nb], ah[s], bh);
                mma_bf16(c[nb], al[s], bh);
                mma_bf16(c[nb], ah[s], bl);
            }
        }
    }

    // Epilogue
    const int r0 = m0 + 16 * w + g;
    const int r1 = r0 + 8;
    #pragma unroll
    for (int nb = 0; nb < 24; nb++) {
        int which = nb >> 3;
        int col   = (nb & 7) * 8 + 2 * tq;
        const float* bias = (which == 0) ? bq : (which == 1) ? bk : bv;
        __nv_bfloat16* Ch = (which == 0) ? g_Qh : (which == 1) ? g_Kh : g_Vh;
        __nv_bfloat16* Cl = (which == 0) ? g_Ql : (which == 1) ? g_Kl : g_Vl;
        float b0 = bias[col], b1 = bias[col + 1];
        unsigned short h0, l0, h1, l1;
        split_bf16(c[nb][0] + b0, h0, l0);
        split_bf16(c[nb][1] + b1, h1, l1);
        *(uint32_t*)(Ch + (size_t)r0 * DH + col) = (uint32_t)h0 | ((uint32_t)h1 << 16);
        *(uint32_t*)(Cl + (size_t)r0 * DH + col) = (uint32_t)l0 | ((uint32_t)l1 << 16);
        split_bf16(c[nb][2] + b0, h0, l0);
        split_bf16(c[nb][3] + b1, h1, l1);
        *(uint32_t*)(Ch + (size_t)r1 * DH + col) = (uint32_t)h0 | ((uint32_t)h1 << 16);
        *(uint32_t*)(Cl + (size_t)r1 * DH + col) = (uint32_t)l0 | ((uint32_t)l1 << 16);
    }
}

// ---------------------------------------------------------------------------
// Kernel 2: split-KV HMMA flash attention with cp.async double buffering.
// One CTA = (b, q-tile 64, kv-chunk of <=16 tiles). 128 threads.
// ---------------------------------------------------------------------------
#define SM_QH 0
#define SM_QL 8192
#define SM_KV 16384                    // 2 stages x 32768 (KH,KL,VH,VL)
#define SMEM_ATTN (16384 + 2 * 32768)  // 81920

__global__ __launch_bounds__(128) void attn_part_kernel()
{
    extern __shared__ char smc[];
    const uint32_t smb = smem_u32(smc);

    const int tid  = threadIdx.x;
    const int w    = tid >> 5;
    const int lane = tid & 31;
    const int g    = lane >> 2;
    const int tq   = lane & 3;

    const int id = blockIdx.x;
    const int b  = id / 160;
    const int r  = id % 160;
    int qt, ch;
    if      (r <  64) { qt = r;              ch = 0; }
    else if (r < 112) { qt = 16 + (r - 64);  ch = 1; }
    else if (r < 144) { qt = 32 + (r - 112); ch = 2; }
    else              { qt = 48 + (r - 144); ch = 3; }
    const int k_lo = 16 * ch;
    const int k_hi = min(qt, 16 * ch + 15);
    const int slot = (b * 64 + qt) * 4 + ch;
    const int q0   = qt * 64;

    // prefetch lambda: KV tile kt -> stage st
    auto prefetch = [&](int kt, int st) {
        const int k0 = kt * 64;
        const uint32_t base = smb + SM_KV + st * 32768;
        const char* srck_h = (const char*)(g_Kh + ((size_t)b * TSEQ + k0) * DH);
        const char* srck_l = (const char*)(g_Kl + ((size_t)b * TSEQ + k0) * DH);
        const char* srcv_h = (const char*)(g_Vh + ((size_t)b * TSEQ + k0) * DH);
        const char* srcv_l = (const char*)(g_Vl + ((size_t)b * TSEQ + k0) * DH);
        #pragma unroll
        for (int t = 0; t < 4; t++) {
            int e = tid + t * 128;              // 0..511 (16B units)
            uint32_t bo = SWZ((uint32_t)e * 16);
            CP_ASYNC16(base         + bo, srck_h + e * 16);
            CP_ASYNC16(base + 8192  + bo, srck_l + e * 16);
            CP_ASYNC16(base + 16384 + bo, srcv_h + e * 16);
            CP_ASYNC16(base + 24576 + bo, srcv_l + e * 16);
        }
    };

    // ---- load Q tile (hi/lo) + prologue prefetch ----
    prefetch(k_lo, 0);
    CP_COMMIT();
    {
        const uint4* sqh = (const uint4*)(g_Qh + ((size_t)b * TSEQ + q0) * DH);
        const uint4* sql = (const uint4*)(g_Ql + ((size_t)b * TSEQ + q0) * DH);
        #pragma unroll
        for (int t = 0; t < 4; t++) {
            int e = tid + t * 128;
            uint32_t bo = (uint32_t)e * 16;
            *(uint4*)(smc + SM_QH + SWZ(bo)) = sqh[e];
            *(uint4*)(smc + SM_QL + SWZ(bo)) = sql[e];
        }
    }
    __syncthreads();

    // ---- Q fragments (persist) ----
    uint32_t qh[4][4], ql[4][4];
    {
        int arow = 16 * w + (lane & 15);
        int kh8  = (lane >> 4) & 1;
        #pragma unroll
        for (int s = 0; s < 4; s++) {
            uint32_t off = SWZ((uint32_t)(arow * 128 + s * 32 + kh8 * 16));
            LDSM_X4(qh[s], smb + SM_QH + off);
            LDSM_X4(ql[s], smb + SM_QL + off);
        }
    }

    float O[8][4];
    #pragma unroll
    for (int n = 0; n < 8; n++)
        #pragma unroll
        for (int e = 0; e < 4; e++) O[n][e] = 0.f;
    float m0r = -1e30f, m1r = -1e30f, l0 = 0.f, l1 = 0.f;

    const int brow = lane & 7;
    const int bh8  = (lane >> 3) & 1;
    const int vrow = lane & 15;

    for (int kt = k_lo; kt <= k_hi; kt++) {
        const int st = (kt - k_lo) & 1;
        if (kt < k_hi) {
            prefetch(kt + 1, st ^ 1);
            CP_COMMIT();
            CP_WAIT(1);
        } else {
            CP_WAIT(0);
        }
        __syncthreads();

        const uint32_t KH = smb + SM_KV + st * 32768;
        const uint32_t KL = KH + 8192;
        const uint32_t VH = KH + 16384;
        const uint32_t VL = KH + 24576;

        // ---- S = Q K^T (3-term compensation) ----
        float C[8][4];
        #pragma unroll
        for (int j = 0; j < 8; j++)
            #pragma unroll
            for (int e = 0; e < 4; e++) C[j][e] = 0.f;

        #pragma unroll
        for (int j = 0; j < 8; j++) {
            #pragma unroll
            for (int s = 0; s < 4; s++) {
                uint32_t off = SWZ((uint32_t)((8 * j + brow) * 128 + s * 32 + bh8 * 16));
                uint32_t bh[2], bl[2];
                LDSM_X2(bh, KH + off);
                LDSM_X2(bl, KL + off);
                mma_bf16(C[j], qh[s], bh);
                mma_bf16(C[j], ql[s], bh);
                mma_bf16(C[j], qh[s], bl);
            }
        }

        // ---- causal mask (diagonal tile only) ----
        if (kt == qt) {
            int r0l = 16 * w + g;
            int r1l = r0l + 8;
            #pragma unroll
            for (int j = 0; j < 8; j++) {
                int col = 8 * j + 2 * tq;
                if (col     > r0l) C[j][0] = -1e30f;
                if (col + 1 > r0l) C[j][1] = -1e30f;
                if (col     > r1l) C[j][2] = -1e30f;
                if (col + 1 > r1l) C[j][3] = -1e30f;
            }
        }

        // ---- online softmax ----
        float mx0 = -1e30f, mx1 = -1e30f;
        #pragma unroll
        for (int j = 0; j < 8; j++) {
            mx0 = fmaxf(mx0, fmaxf(C[j][0], C[j][1]));
            mx1 = fmaxf(mx1, fmaxf(C[j][2], C[j][3]));
        }
        mx0 = fmaxf(mx0, __shfl_xor_sync(0xffffffffu, mx0, 1));
        mx0 = fmaxf(mx0, __shfl_xor_sync(0xffffffffu, mx0, 2));
        mx1 = fmaxf(mx1, __shfl_xor_sync(0xffffffffu, mx1, 1));
        mx1 = fmaxf(mx1, __shfl_xor_sync(0xffffffffu, mx1, 2));

        float mn0 = fmaxf(m0r, mx0), mn1 = fmaxf(m1r, mx1);
        float scl0 = exp2ap((m0r - mn0) * L2E);
        float scl1 = exp2ap((m1r - mn1) * L2E);
        m0r = mn0; m1r = mn1;
        float base0 = mn0 * L2E, base1 = mn1 * L2E;

        float s0 = 0.f, s1 = 0.f;
        uint32_t ph[4][4], pl[4][4];
        #pragma unroll
        for (int j = 0; j < 8; j++) {
            float p00 = exp2ap(fmaf(C[j][0], L2E, -base0));
            float p01 = exp2ap(fmaf(C[j][1], L2E, -base0));
            float p10 = exp2ap(fmaf(C[j][2], L2E, -base1));
            float p11 = exp2ap(fmaf(C[j][3], L2E, -base1));
            s0 += p00 + p01;
            s1 += p10 + p11;

            __nv_bfloat162 H0 = __floats2bfloat162_rn(p00, p01);
            __nv_bfloat162 H1 = __floats2bfloat162_rn(p10, p11);
            __nv_bfloat162 L0 = __floats2bfloat162_rn(p00 - __bfloat162float(H0.x),
                                                      p01 - __bfloat162float(H0.y));
            __nv_bfloat162 L1 = __floats2bfloat162_rn(p10 - __bfloat162float(H1.x),
                                                      p11 - __bfloat162float(H1.y));
            int sp  = j >> 1;
            int rlo = (j & 1) * 2;
            ph[sp][rlo]     = *(uint32_t*)&H0;
            ph[sp][rlo + 1] = *(uint32_t*)&H1;
            pl[sp][rlo]     = *(uint32_t*)&L0;
            pl[sp][rlo + 1] = *(uint32_t*)&L1;
        }
        s0 += __shfl_xor_sync(0xffffffffu, s0, 1);
        s0 += __shfl_xor_sync(0xffffffffu, s0, 2);
        s1 += __shfl_xor_sync(0xffffffffu, s1, 1);
        s1 += __shfl_xor_sync(0xffffffffu, s1, 2);
        l0 = l0 * scl0 + s0;
        l1 = l1 * scl1 + s1;

        #pragma unroll
        for (int n = 0; n < 8; n++) {
            O[n][0] *= scl0; O[n][1] *= scl0;
            O[n][2] *= scl1; O[n][3] *= scl1;
        }

        // ---- O += P V (V row-major, ldmatrix.trans) ----
        #pragma unroll
        for (int n = 0; n < 8; n++) {
            #pragma unroll
            for (int s = 0; s < 4; s++) {
                uint32_t off = SWZ((uint32_t)((16 * s + vrow) * 128 + n * 16));
                uint32_t vh[2], vl[2];
                LDSM_X2_T(vh, VH + off);
                LDSM_X2_T(vl, VL + off);
                mma_bf16(O[n], ph[s], vh);
                mma_bf16(O[n], pl[s], vh);
                mma_bf16(O[n], ph[s], vl);
            }
        }
        __syncthreads();   // all reads of this stage done before reuse
    }

    // ---- write partials ----
    {
        float* pO = g_pO + (size_t)slot * 64 * 64;
        int r0l = 16 * w + g;
        int r1l = r0l + 8;
        #pragma unroll
        for (int n = 0; n < 8; n++) {
            int col = 8 * n + 2 * tq;
            *(float2*)(pO + r0l * 64 + col) = make_float2(O[n][0], O[n][1]);
            *(float2*)(pO + r1l * 64 + col) = make_float2(O[n][2], O[n][3]);
        }
        if (tq == 0) {
            g_pm[slot * 64 + r0l] = m0r;
            g_pm[slot * 64 + r1l] = m1r;
            g_pl[slot * 64 + r0l] = l0;
            g_pl[slot * 64 + r1l] = l1;
        }
    }
}

// ---------------------------------------------------------------------------
// Kernel 3: combine split-KV partials. One CTA per (b, qt). 128 threads.
// ---------------------------------------------------------------------------
__global__ __launch_bounds__(128) void attn_combine_kernel(float* __restrict__ Out)
{
    const int blk = blockIdx.x;
    const int b   = blk >> 6;
    const int qt  = blk & 63;
    const int t   = threadIdx.x;
    const int row = t >> 1;
    const int hf  = t & 1;

    const int nc    = (qt >> 4) + 1;
    const int sbase = (b * 64 + qt) * 4;

    float mv[4], lv[4];
    float m = -1e30f;
    for (int c = 0; c < nc; c++) {
        mv[c] = g_pm[(sbase + c) * 64 + row];
        lv[c] = g_pl[(sbase + c) * 64 + row];
        m = fmaxf(m, mv[c]);
    }
    float l = 0.f;
    float wc[4];
    for (int c = 0; c < nc; c++) {
        wc[c] = exp2ap((mv[c] - m) * L2E);
        l += wc[c] * lv[c];
    }
    float inv = 8.0f / l;

    float* dst = Out + ((size_t)b * TSEQ + (size_t)qt * 64 + row) * DH + 32 * hf;
    #pragma unroll
    for (int j = 0; j < 8; j++) {
        int col = 32 * hf + 4 * j;
        float4 acc = make_float4(0.f, 0.f, 0.f, 0.f);
        for (int c = 0; c < nc; c++) {
            const float4 v = *(const float4*)(g_pO + (size_t)(sbase + c) * 4096 + row * 64 + col);
            acc.x += wc[c] * v.x; acc.y += wc[c] * v.y;
            acc.z += wc[c] * v.z; acc.w += wc[c] * v.w;
        }
        *(float4*)(dst + 4 * j) = make_float4(acc.x * inv, acc.y * inv,
                                              acc.z * inv, acc.w * inv);
    }
}

// ---------------------------------------------------------------------------
// Launch: inputs per metadata order: x, Wq_w, Wq_b, Wk_w, Wk_b, Wv_w, Wv_b
// ---------------------------------------------------------------------------
extern "C" void kernel_launch(void* const* d_in, const int* in_sizes, int n_in,
                              void* d_out, int out_size)
{
    const float* x  = (const float*)d_in[0];
    const float* Wq = (const float*)d_in[1];
    const float* bq = (const float*)d_in[2];
    const float* Wk = (const float*)d_in[3];
    const float* bk = (const float*)d_in[4];
    const float* Wv = (const float*)d_in[5];
    const float* bv = (const float*)d_in[6];
    float* out = (float*)d_out;

    wsplit_kernel<<<384, 256>>>(Wq, Wk, Wv);

    cudaFuncSetAttribute(qkv_fused_kernel,
                         cudaFuncAttributeMaxDynamicSharedMemorySize,
                         QF_SMEM);
    qkv_fused_kernel<<<128, 256, QF_SMEM>>>(x, bq, bk, bv);

    cudaFuncSetAttribute(attn_part_kernel,
                         cudaFuncAttributeMaxDynamicSharedMemorySize,
                         SMEM_ATTN);
    attn_part_kernel<<<640, 128, SMEM_ATTN>>>();

    attn_combine_kernel<<<256, 128>>>(out);
}